// round 12
// baseline (speedup 1.0000x reference)
#include <cuda_runtime.h>
#include <math.h>

#define NCLUST 196
#define DIM 256
#define NROWS 262144
#define TEMP_INV 2.0f        // 1/TEMPERATURE
#define EPSV 1e-12f

// -------- scratch (device globals; no allocation allowed) --------
struct Scratch {
    float sums[2][NCLUST * DIM];   // [q,k] raw segment sums
    int counts[NCLUST];
    int cursor[NCLUST];
    int done;
    int nzero;
    float loss_sum;
};
__device__ Scratch g_s;                         // zeroed by ONE memset
__device__ unsigned g_pack[NROWS];              // (label<<18) | row

// -------- 1. histogram. 64 blocks (minimize contended global atomics) ----
__global__ void k_hist(const int* __restrict__ labels) {
    __shared__ int s_cnt[NCLUST];
    for (int i = threadIdx.x; i < NCLUST; i += blockDim.x) s_cnt[i] = 0;
    __syncthreads();
    const int4* l4 = (const int4*)labels;
    for (int r = blockIdx.x * blockDim.x + threadIdx.x; r < NROWS / 4;
         r += gridDim.x * blockDim.x) {
        int4 v = l4[r];
        atomicAdd(&s_cnt[v.x], 1);
        atomicAdd(&s_cnt[v.y], 1);
        atomicAdd(&s_cnt[v.z], 1);
        atomicAdd(&s_cnt[v.w], 1);
    }
    __syncthreads();
    for (int i = threadIdx.x; i < NCLUST; i += blockDim.x)
        if (s_cnt[i]) atomicAdd(&g_s.counts[i], s_cnt[i]);
}

// -------- 2. scatter (scan fused). 128 blocks x 256, 2048 rows/block ----
__global__ void __launch_bounds__(256) k_scatter(const int* __restrict__ labels) {
    __shared__ int s_hist[NCLUST];
    __shared__ int s_base[NCLUST];
    __shared__ int s_scan[256];
    const int t = threadIdx.x;

    int cv = (t < NCLUST) ? g_s.counts[t] : 0;
    s_scan[t] = cv;
    for (int i = t; i < NCLUST; i += 256) s_hist[i] = 0;
    // block 0 precomputes n_zero for k_loss's final mean
    if (blockIdx.x == 0 && t < NCLUST && cv == 0) atomicAdd(&g_s.nzero, 1);
    __syncthreads();
#pragma unroll
    for (int off = 1; off < 256; off <<= 1) {
        int add = (t >= off) ? s_scan[t - off] : 0;
        __syncthreads();
        s_scan[t] += add;
        __syncthreads();
    }

    const int r0 = blockIdx.x * 2048;
    int labs[8], rk[8];
#pragma unroll
    for (int u = 0; u < 8; u++) labs[u] = labels[r0 + u * 256 + t];
#pragma unroll
    for (int u = 0; u < 8; u++) rk[u] = atomicAdd(&s_hist[labs[u]], 1);
    __syncthreads();
    if (t < NCLUST) {
        int h = s_hist[t];
        if (h) s_base[t] = (s_scan[t] - cv) + atomicAdd(&g_s.cursor[t], h);
    }
    __syncthreads();
#pragma unroll
    for (int u = 0; u < 8; u++) {
        int c = labs[u];
        int p = s_base[c] + rk[u];
        g_pack[p] = ((unsigned)c << 18) | (unsigned)(r0 + u * 256 + t);
    }
}

// -------- 3. segment sums over label-sorted rows (hot kernel) --------
__global__ void __launch_bounds__(256, 5) k_segsum(const float* __restrict__ xq,
                                                   const float* __restrict__ xk) {
    const float* __restrict__ x = blockIdx.y ? xk : xq;
    float* sums = &g_s.sums[blockIdx.y][0];
    const int t = threadIdx.x;
    const int dq = (t & 63) * 4;      // dim-quad base
    const int sub = t >> 6;           // 0..3
    const int start = blockIdx.x * 256;

    int cur = (int)(g_pack[start + sub] >> 18);
    float4 acc = make_float4(0.f, 0.f, 0.f, 0.f);

    for (int it = 0; it < 64; it += 8) {
        unsigned pk[8];
        float4 v[8];
#pragma unroll
        for (int u = 0; u < 8; u++)
            pk[u] = g_pack[start + sub + (it + u) * 4];
#pragma unroll
        for (int u = 0; u < 8; u++)
            v[u] = __ldcs((const float4*)&x[(size_t)(pk[u] & 0x3FFFFu) * DIM + dq]);
#pragma unroll
        for (int u = 0; u < 8; u++) {
            int lb = (int)(pk[u] >> 18);
            if (lb != cur) {
                float* dst = &sums[cur * DIM + dq];
                atomicAdd(dst + 0, acc.x);
                atomicAdd(dst + 1, acc.y);
                atomicAdd(dst + 2, acc.z);
                atomicAdd(dst + 3, acc.w);
                acc = make_float4(0.f, 0.f, 0.f, 0.f);
                cur = lb;
            }
            acc.x += v[u].x;
            acc.y += v[u].y;
            acc.z += v[u].z;
            acc.w += v[u].w;
        }
    }
    float* dst = &sums[cur * DIM + dq];
    atomicAdd(dst + 0, acc.x);
    atomicAdd(dst + 1, acc.y);
    atomicAdd(dst + 2, acc.z);
    atomicAdd(dst + 3, acc.w);
}

// -------- 4. loss on RAW sums, 4 i-rows/block, grid 49 x 512 thr -------
// dot(c_i,c_j) = dot(s_i,s_j)*inv_i*inv_j.  Each loaded j-row is reused
// for 4 dots + 1 norm; 16 warps, 3 rounds of 4 j's (20 shfl trees/round).
__global__ void __launch_bounds__(512) k_loss(float* out) {
    const int ib = blockIdx.x * 4;
    const int tid = threadIdx.x;
    const int lane = tid & 31, w = tid >> 5;   // 16 warps
    __shared__ float s_q[4][DIM];
    __shared__ float s_k[4][DIM];
    __shared__ float s_row[4][NCLUST];
    __shared__ float s_n[NCLUST];
    __shared__ float s_dk[4], s_nk[4];
    __shared__ float s_r[4][16];
    __shared__ float s_mx[4], s_sum[4];

    const float* sq = &g_s.sums[0][0];
    const float* sk = &g_s.sums[1][0];

    for (int e = tid; e < 4 * DIM; e += 512) {
        int r = e >> 8, d = e & 255;
        s_q[r][d] = sq[(ib + r) * DIM + d];
        s_k[r][d] = sk[(ib + r) * DIM + d];
    }
    __syncthreads();

    float4 qa[4], qb[4];
#pragma unroll
    for (int r = 0; r < 4; r++) {
        qa[r] = ((const float4*)s_q[r])[lane];
        qb[r] = ((const float4*)s_q[r])[32 + lane];
    }

    // 3 rounds x 4 j's: j = w + (r*4+g)*16, covers 0..191
#pragma unroll
    for (int r = 0; r < 3; r++) {
        float4 va[4], vb[4];
        float p[4][4], nn[4];
#pragma unroll
        for (int g = 0; g < 4; g++) {
            const float4* vj = (const float4*)&sq[(w + (r * 4 + g) * 16) * DIM];
            va[g] = vj[lane];
            vb[g] = vj[32 + lane];
        }
#pragma unroll
        for (int g = 0; g < 4; g++) {
            nn[g] = va[g].x * va[g].x + va[g].y * va[g].y + va[g].z * va[g].z + va[g].w * va[g].w
                  + vb[g].x * vb[g].x + vb[g].y * vb[g].y + vb[g].z * vb[g].z + vb[g].w * vb[g].w;
#pragma unroll
            for (int rr = 0; rr < 4; rr++)
                p[rr][g] = va[g].x * qa[rr].x + va[g].y * qa[rr].y + va[g].z * qa[rr].z + va[g].w * qa[rr].w
                         + vb[g].x * qb[rr].x + vb[g].y * qb[rr].y + vb[g].z * qb[rr].z + vb[g].w * qb[rr].w;
        }
#pragma unroll
        for (int off = 16; off > 0; off >>= 1) {
#pragma unroll
            for (int g = 0; g < 4; g++) {
                nn[g] += __shfl_xor_sync(0xFFFFFFFFu, nn[g], off);
#pragma unroll
                for (int rr = 0; rr < 4; rr++)
                    p[rr][g] += __shfl_xor_sync(0xFFFFFFFFu, p[rr][g], off);
            }
        }
        if (lane == 0) {
#pragma unroll
            for (int g = 0; g < 4; g++) {
                int j = w + (r * 4 + g) * 16;
                s_n[j] = nn[g];
#pragma unroll
                for (int rr = 0; rr < 4; rr++) s_row[rr][j] = p[rr][g];
            }
        }
    }
    // tail: j = 192 + w for w < 4
    if (w < 4) {
        const int j = 192 + w;
        const float4* vj = (const float4*)&sq[j * DIM];
        float4 va = vj[lane], vb = vj[32 + lane];
        float p[4], nn;
        nn = va.x * va.x + va.y * va.y + va.z * va.z + va.w * va.w
           + vb.x * vb.x + vb.y * vb.y + vb.z * vb.z + vb.w * vb.w;
#pragma unroll
        for (int rr = 0; rr < 4; rr++)
            p[rr] = va.x * qa[rr].x + va.y * qa[rr].y + va.z * qa[rr].z + va.w * qa[rr].w
                  + vb.x * qb[rr].x + vb.y * qb[rr].y + vb.z * qb[rr].z + vb.w * qb[rr].w;
#pragma unroll
        for (int off = 16; off > 0; off >>= 1) {
            nn += __shfl_xor_sync(0xFFFFFFFFu, nn, off);
#pragma unroll
            for (int rr = 0; rr < 4; rr++)
                p[rr] += __shfl_xor_sync(0xFFFFFFFFu, p[rr], off);
        }
        if (lane == 0) {
            s_n[j] = nn;
#pragma unroll
            for (int rr = 0; rr < 4; rr++) s_row[rr][j] = p[rr];
        }
    }
    // diagonals: warps 4..7 -> row sel = w-4: dot(q_sel, k_sel), ||k_sel||^2
    if (w >= 4 && w < 8) {
        const int sel = w - 4;
        const float4* vj = (const float4*)s_k[sel];
        float4 va = vj[lane], vb = vj[32 + lane];
        float p = va.x * qa[sel].x + va.y * qa[sel].y + va.z * qa[sel].z + va.w * qa[sel].w
                + vb.x * qb[sel].x + vb.y * qb[sel].y + vb.z * qb[sel].z + vb.w * qb[sel].w;
        float nn = va.x * va.x + va.y * va.y + va.z * va.z + va.w * va.w
                 + vb.x * vb.x + vb.y * vb.y + vb.z * vb.z + vb.w * vb.w;
#pragma unroll
        for (int off = 16; off > 0; off >>= 1) {
            p += __shfl_xor_sync(0xFFFFFFFFu, p, off);
            nn += __shfl_xor_sync(0xFFFFFFFFu, nn, off);
        }
        if (lane == 0) { s_dk[sel] = p; s_nk[sel] = nn; }
    }
    __syncthreads();

    // scale + mask, per thread column tid for all 4 rows
    float inv_i[4];
#pragma unroll
    for (int rr = 0; rr < 4; rr++)
        inv_i[rr] = 1.0f / fmaxf(sqrtf(s_n[ib + rr]), EPSV);
    float rv[4] = {-1e30f, -1e30f, -1e30f, -1e30f};
    if (tid < NCLUST) {
        float invj = 1.0f / fmaxf(sqrtf(s_n[tid]), EPSV);
        int zero = (g_s.counts[tid] == 0);
#pragma unroll
        for (int rr = 0; rr < 4; rr++) {
            float v;
            if (tid == ib + rr)
                v = s_dk[rr] * inv_i[rr] / fmaxf(sqrtf(s_nk[rr]), EPSV) * TEMP_INV;
            else
                v = s_row[rr][tid] * inv_i[rr] * invj * TEMP_INV;
            if (zero) v = -10.0f;
            rv[rr] = v;
            s_row[rr][tid] = v;
        }
    }
    __syncthreads();

    // joint max reduce (4 rows)
    float v[4] = {rv[0], rv[1], rv[2], rv[3]};
#pragma unroll
    for (int off = 16; off > 0; off >>= 1)
#pragma unroll
        for (int rr = 0; rr < 4; rr++)
            v[rr] = fmaxf(v[rr], __shfl_xor_sync(0xFFFFFFFFu, v[rr], off));
    if (lane == 0)
#pragma unroll
        for (int rr = 0; rr < 4; rr++) s_r[rr][w] = v[rr];
    __syncthreads();
    if (tid < 4) {
        float m = s_r[tid][0];
        for (int k = 1; k < 16; k++) m = fmaxf(m, s_r[tid][k]);
        s_mx[tid] = m;
    }
    __syncthreads();

    float e[4];
#pragma unroll
    for (int rr = 0; rr < 4; rr++)
        e[rr] = (tid < NCLUST) ? __expf(s_row[rr][tid] - s_mx[rr]) : 0.0f;
#pragma unroll
    for (int off = 16; off > 0; off >>= 1)
#pragma unroll
        for (int rr = 0; rr < 4; rr++)
            e[rr] += __shfl_xor_sync(0xFFFFFFFFu, e[rr], off);
    if (lane == 0)
#pragma unroll
        for (int rr = 0; rr < 4; rr++) s_r[rr][w] = e[rr];
    __syncthreads();
    if (tid < 4) {
        float t0 = 0.f;
        for (int k = 0; k < 16; k++) t0 += s_r[tid][k];
        s_sum[tid] = t0;
    }
    __syncthreads();

    if (tid == 0) {
        float loss = 0.0f;
#pragma unroll
        for (int rr = 0; rr < 4; rr++)
            if (g_s.counts[ib + rr] != 0)
                loss += -s_row[rr][ib + rr] + s_mx[rr] + logf(s_sum[rr]);
        if (loss != 0.0f) atomicAdd(&g_s.loss_sum, loss);
        __threadfence();
        int ticket = atomicAdd(&g_s.done, 1);
        if (ticket == NCLUST / 4 - 1) {
            float tot = atomicAdd(&g_s.loss_sum, 0.0f);
            out[0] = tot / ((float)NCLUST - (float)g_s.nzero);
        }
    }
}

extern "C" void kernel_launch(void* const* d_in, const int* in_sizes, int n_in,
                              void* d_out, int out_size) {
    const float* im_q = (const float*)d_in[0];
    const float* im_k = (const float*)d_in[1];
    const int* labels = (const int*)d_in[2];
    float* out = (float*)d_out;

    void* p_s = 0;
    cudaGetSymbolAddress(&p_s, g_s);
    cudaMemsetAsync(p_s, 0, sizeof(Scratch));

    k_hist<<<64, 256>>>(labels);
    k_scatter<<<128, 256>>>(labels);
    dim3 gs(NROWS / 256, 2);
    k_segsum<<<gs, 256>>>(im_q, im_k);
    k_loss<<<NCLUST / 4, 512>>>(out);
}

// round 13
// speedup vs baseline: 1.0345x; 1.0345x over previous
#include <cuda_runtime.h>
#include <math.h>

#define NCLUST 196
#define DIM 256
#define NROWS 262144
#define TEMP_INV 2.0f        // 1/TEMPERATURE
#define EPSV 1e-12f

// -------- scratch (device globals; no allocation allowed) --------
struct Scratch {
    float sums[2][NCLUST * DIM];   // [q,k] raw segment sums
    int counts[NCLUST];
    int cursor[NCLUST];
    int done;
    int nzero;
    float loss_sum;
};
__device__ Scratch g_s;                         // zeroed by ONE memset
__device__ unsigned g_pack[NROWS];              // (label<<18) | row

// -------- 1. histogram. 64 blocks (minimize contended global atomics) ----
__global__ void k_hist(const int* __restrict__ labels) {
    __shared__ int s_cnt[NCLUST];
    for (int i = threadIdx.x; i < NCLUST; i += blockDim.x) s_cnt[i] = 0;
    __syncthreads();
    const int4* l4 = (const int4*)labels;
    for (int r = blockIdx.x * blockDim.x + threadIdx.x; r < NROWS / 4;
         r += gridDim.x * blockDim.x) {
        int4 v = l4[r];
        atomicAdd(&s_cnt[v.x], 1);
        atomicAdd(&s_cnt[v.y], 1);
        atomicAdd(&s_cnt[v.z], 1);
        atomicAdd(&s_cnt[v.w], 1);
    }
    __syncthreads();
    for (int i = threadIdx.x; i < NCLUST; i += blockDim.x)
        if (s_cnt[i]) atomicAdd(&g_s.counts[i], s_cnt[i]);
}

// -------- 2. scatter (scan fused). 128 blocks x 256, 2048 rows/block ----
__global__ void __launch_bounds__(256) k_scatter(const int* __restrict__ labels) {
    __shared__ int s_hist[NCLUST];
    __shared__ int s_base[NCLUST];
    __shared__ int s_scan[256];
    const int t = threadIdx.x;

    int cv = (t < NCLUST) ? g_s.counts[t] : 0;
    s_scan[t] = cv;
    for (int i = t; i < NCLUST; i += 256) s_hist[i] = 0;
    // block 0 precomputes n_zero for k_loss's final mean
    if (blockIdx.x == 0 && t < NCLUST && cv == 0) atomicAdd(&g_s.nzero, 1);
    __syncthreads();
#pragma unroll
    for (int off = 1; off < 256; off <<= 1) {
        int add = (t >= off) ? s_scan[t - off] : 0;
        __syncthreads();
        s_scan[t] += add;
        __syncthreads();
    }

    const int r0 = blockIdx.x * 2048;
    int labs[8], rk[8];
#pragma unroll
    for (int u = 0; u < 8; u++) labs[u] = labels[r0 + u * 256 + t];
#pragma unroll
    for (int u = 0; u < 8; u++) rk[u] = atomicAdd(&s_hist[labs[u]], 1);
    __syncthreads();
    if (t < NCLUST) {
        int h = s_hist[t];
        if (h) s_base[t] = (s_scan[t] - cv) + atomicAdd(&g_s.cursor[t], h);
    }
    __syncthreads();
#pragma unroll
    for (int u = 0; u < 8; u++) {
        int c = labs[u];
        int p = s_base[c] + rk[u];
        g_pack[p] = ((unsigned)c << 18) | (unsigned)(r0 + u * 256 + t);
    }
}

// -------- 3. segment sums over label-sorted rows (hot kernel) --------
__global__ void __launch_bounds__(256, 5) k_segsum(const float* __restrict__ xq,
                                                   const float* __restrict__ xk) {
    const float* __restrict__ x = blockIdx.y ? xk : xq;
    float* sums = &g_s.sums[blockIdx.y][0];
    const int t = threadIdx.x;
    const int dq = (t & 63) * 4;      // dim-quad base
    const int sub = t >> 6;           // 0..3
    const int start = blockIdx.x * 256;

    int cur = (int)(g_pack[start + sub] >> 18);
    float4 acc = make_float4(0.f, 0.f, 0.f, 0.f);

    for (int it = 0; it < 64; it += 8) {
        unsigned pk[8];
        float4 v[8];
#pragma unroll
        for (int u = 0; u < 8; u++)
            pk[u] = g_pack[start + sub + (it + u) * 4];
#pragma unroll
        for (int u = 0; u < 8; u++)
            v[u] = __ldcs((const float4*)&x[(size_t)(pk[u] & 0x3FFFFu) * DIM + dq]);
#pragma unroll
        for (int u = 0; u < 8; u++) {
            int lb = (int)(pk[u] >> 18);
            if (lb != cur) {
                float* dst = &sums[cur * DIM + dq];
                atomicAdd(dst + 0, acc.x);
                atomicAdd(dst + 1, acc.y);
                atomicAdd(dst + 2, acc.z);
                atomicAdd(dst + 3, acc.w);
                acc = make_float4(0.f, 0.f, 0.f, 0.f);
                cur = lb;
            }
            acc.x += v[u].x;
            acc.y += v[u].y;
            acc.z += v[u].z;
            acc.w += v[u].w;
        }
    }
    float* dst = &sums[cur * DIM + dq];
    atomicAdd(dst + 0, acc.x);
    atomicAdd(dst + 1, acc.y);
    atomicAdd(dst + 2, acc.z);
    atomicAdd(dst + 3, acc.w);
}

// -------- 4. loss on RAW sums, 1024 thr, two 3-j rounds + tail ----------
// dot(c_i,c_j) = dot(s_i,s_j)*inv_i*inv_j. 2 i-rows per block, grid 98.
// 32 warps: warp w owns j in {w, w+32, ...}; 9 shfl trees interleave/round.
__global__ void __launch_bounds__(1024) k_loss(float* out) {
    const int i0 = blockIdx.x * 2;
    const int i1 = i0 + 1;
    const int tid = threadIdx.x;
    const int lane = tid & 31, w = tid >> 5;
    __shared__ float s_q0[DIM], s_q1[DIM];
    __shared__ float s_row0[NCLUST], s_row1[NCLUST];
    __shared__ float s_n[NCLUST];
    __shared__ float s_dkraw[2], s_nk[2];
    __shared__ float s_r0[32], s_r1[32];
    __shared__ float s_mx0, s_mx1, s_sum0, s_sum1;

    const float* sq = &g_s.sums[0][0];
    const float* sk = &g_s.sums[1][0];

    if (tid < DIM) {
        s_q0[tid] = sq[i0 * DIM + tid];
        s_q1[tid] = sq[i1 * DIM + tid];
    }
    __syncthreads();

    const float4* q0v = (const float4*)s_q0;
    const float4* q1v = (const float4*)s_q1;
    const float4 a0 = q0v[lane], b0 = q0v[32 + lane];
    const float4 a1 = q1v[lane], b1 = q1v[32 + lane];

    // rounds r=0,1: j = w + (r*3+g)*32, g=0..2 (all < 192).
#pragma unroll
    for (int r = 0; r < 2; r++) {
        float4 va[3], vb[3];
        float p0[3], p1[3], nn[3];
#pragma unroll
        for (int g = 0; g < 3; g++) {
            const float4* vj = (const float4*)&sq[(w + (r * 3 + g) * 32) * DIM];
            va[g] = vj[lane];
            vb[g] = vj[32 + lane];
        }
#pragma unroll
        for (int g = 0; g < 3; g++) {
            p0[g] = va[g].x * a0.x + va[g].y * a0.y + va[g].z * a0.z + va[g].w * a0.w
                  + vb[g].x * b0.x + vb[g].y * b0.y + vb[g].z * b0.z + vb[g].w * b0.w;
            p1[g] = va[g].x * a1.x + va[g].y * a1.y + va[g].z * a1.z + va[g].w * a1.w
                  + vb[g].x * b1.x + vb[g].y * b1.y + vb[g].z * b1.z + vb[g].w * b1.w;
            nn[g] = va[g].x * va[g].x + va[g].y * va[g].y + va[g].z * va[g].z + va[g].w * va[g].w
                  + vb[g].x * vb[g].x + vb[g].y * vb[g].y + vb[g].z * vb[g].z + vb[g].w * vb[g].w;
        }
#pragma unroll
        for (int off = 16; off > 0; off >>= 1) {
#pragma unroll
            for (int g = 0; g < 3; g++) {
                p0[g] += __shfl_xor_sync(0xFFFFFFFFu, p0[g], off);
                p1[g] += __shfl_xor_sync(0xFFFFFFFFu, p1[g], off);
                nn[g] += __shfl_xor_sync(0xFFFFFFFFu, nn[g], off);
            }
        }
        if (lane == 0) {
#pragma unroll
            for (int g = 0; g < 3; g++) {
                int j = w + (r * 3 + g) * 32;
                s_row0[j] = p0[g];
                s_row1[j] = p1[g];
                s_n[j] = nn[g];
            }
        }
    }
    // tail: j = 192 + w for w < 4
    if (w < 4) {
        const int j = w + 192;
        const float4* vj = (const float4*)&sq[j * DIM];
        float4 va = vj[lane], vb = vj[32 + lane];
        float p0 = va.x * a0.x + va.y * a0.y + va.z * a0.z + va.w * a0.w
                 + vb.x * b0.x + vb.y * b0.y + vb.z * b0.z + vb.w * b0.w;
        float p1 = va.x * a1.x + va.y * a1.y + va.z * a1.z + va.w * a1.w
                 + vb.x * b1.x + vb.y * b1.y + vb.z * b1.z + vb.w * b1.w;
        float nn = va.x * va.x + va.y * va.y + va.z * va.z + va.w * va.w
                 + vb.x * vb.x + vb.y * vb.y + vb.z * vb.z + vb.w * vb.w;
#pragma unroll
        for (int off = 16; off > 0; off >>= 1) {
            p0 += __shfl_xor_sync(0xFFFFFFFFu, p0, off);
            p1 += __shfl_xor_sync(0xFFFFFFFFu, p1, off);
            nn += __shfl_xor_sync(0xFFFFFFFFu, nn, off);
        }
        if (lane == 0) { s_row0[j] = p0; s_row1[j] = p1; s_n[j] = nn; }
    }
    // k-diagonals (warps 4,5)
    if (w == 4 || w == 5) {
        const int sel = w - 4;
        const float4* vj = (const float4*)&sk[(sel ? i1 : i0) * DIM];
        float4 va = vj[lane], vb = vj[32 + lane];
        float4 ca = sel ? a1 : a0, cb = sel ? b1 : b0;
        float p = va.x * ca.x + va.y * ca.y + va.z * ca.z + va.w * ca.w
                + vb.x * cb.x + vb.y * cb.y + vb.z * cb.z + vb.w * cb.w;
        float nn = va.x * va.x + va.y * va.y + va.z * va.z + va.w * va.w
                 + vb.x * vb.x + vb.y * vb.y + vb.z * vb.z + vb.w * vb.w;
#pragma unroll
        for (int off = 16; off > 0; off >>= 1) {
            p += __shfl_xor_sync(0xFFFFFFFFu, p, off);
            nn += __shfl_xor_sync(0xFFFFFFFFu, nn, off);
        }
        if (lane == 0) { s_dkraw[sel] = p; s_nk[sel] = nn; }
    }
    __syncthreads();

    // scale + mask
    const float inv0 = 1.0f / fmaxf(sqrtf(s_n[i0]), EPSV);
    const float inv1 = 1.0f / fmaxf(sqrtf(s_n[i1]), EPSV);
    float r0 = -1e30f, r1 = -1e30f;
    if (tid < NCLUST) {
        float invj = 1.0f / fmaxf(sqrtf(s_n[tid]), EPSV);
        if (tid == i0)
            r0 = s_dkraw[0] * inv0 / fmaxf(sqrtf(s_nk[0]), EPSV) * TEMP_INV;
        else
            r0 = s_row0[tid] * inv0 * invj * TEMP_INV;
        if (tid == i1)
            r1 = s_dkraw[1] * inv1 / fmaxf(sqrtf(s_nk[1]), EPSV) * TEMP_INV;
        else
            r1 = s_row1[tid] * inv1 * invj * TEMP_INV;
        if (g_s.counts[tid] == 0) { r0 = -10.0f; r1 = -10.0f; }
        s_row0[tid] = r0;
        s_row1[tid] = r1;
    }
    __syncthreads();

    float v0 = r0, v1 = r1;
#pragma unroll
    for (int off = 16; off > 0; off >>= 1) {
        v0 = fmaxf(v0, __shfl_xor_sync(0xFFFFFFFFu, v0, off));
        v1 = fmaxf(v1, __shfl_xor_sync(0xFFFFFFFFu, v1, off));
    }
    if (lane == 0) { s_r0[w] = v0; s_r1[w] = v1; }
    __syncthreads();
    if (tid == 0) {
        float m0 = s_r0[0], m1 = s_r1[0];
        for (int k = 1; k < 32; k++) {
            m0 = fmaxf(m0, s_r0[k]);
            m1 = fmaxf(m1, s_r1[k]);
        }
        s_mx0 = m0; s_mx1 = m1;
    }
    __syncthreads();
    float mx0 = s_mx0, mx1 = s_mx1;

    float e0 = (tid < NCLUST) ? __expf(s_row0[tid] - mx0) : 0.0f;
    float e1 = (tid < NCLUST) ? __expf(s_row1[tid] - mx1) : 0.0f;
#pragma unroll
    for (int off = 16; off > 0; off >>= 1) {
        e0 += __shfl_xor_sync(0xFFFFFFFFu, e0, off);
        e1 += __shfl_xor_sync(0xFFFFFFFFu, e1, off);
    }
    if (lane == 0) { s_r0[w] = e0; s_r1[w] = e1; }
    __syncthreads();
    if (tid == 0) {
        float t0 = 0.f, t1 = 0.f;
        for (int k = 0; k < 32; k++) { t0 += s_r0[k]; t1 += s_r1[k]; }
        s_sum0 = t0; s_sum1 = t1;
    }
    __syncthreads();

    if (tid == 0) {
        float loss = 0.0f;
        if (g_s.counts[i0] != 0) loss += -s_row0[i0] + mx0 + logf(s_sum0);
        if (g_s.counts[i1] != 0) loss += -s_row1[i1] + mx1 + logf(s_sum1);
        if (loss != 0.0f) atomicAdd(&g_s.loss_sum, loss);
        __threadfence();
        int ticket = atomicAdd(&g_s.done, 1);
        if (ticket == NCLUST / 2 - 1) {
            float tot = atomicAdd(&g_s.loss_sum, 0.0f);
            out[0] = tot / ((float)NCLUST - (float)g_s.nzero);
        }
    }
}

extern "C" void kernel_launch(void* const* d_in, const int* in_sizes, int n_in,
                              void* d_out, int out_size) {
    const float* im_q = (const float*)d_in[0];
    const float* im_k = (const float*)d_in[1];
    const int* labels = (const int*)d_in[2];
    float* out = (float*)d_out;

    void* p_s = 0;
    cudaGetSymbolAddress(&p_s, g_s);
    cudaMemsetAsync(p_s, 0, sizeof(Scratch));

    k_hist<<<64, 256>>>(labels);
    k_scatter<<<128, 256>>>(labels);
    dim3 gs(NROWS / 256, 2);
    k_segsum<<<gs, 256>>>(im_q, im_k);
    k_loss<<<NCLUST / 2, 1024>>>(out);
}

// round 14
// speedup vs baseline: 1.0609x; 1.0255x over previous
#include <cuda_runtime.h>
#include <math.h>

#define NCLUST 196
#define DIM 256
#define NROWS 262144
#define NCHUNK (NROWS / 256)   // 1024 chunks per matrix
#define TEMP_INV 2.0f          // 1/TEMPERATURE
#define EPSV 1e-12f

// -------- scratch (device globals; no allocation allowed) --------
struct Scratch {
    float sums[2][NCLUST * DIM];   // [q,k] raw segment sums
    int counts[NCLUST];
    int cursor[NCLUST];
    int work;                      // segsum work-steal counter
    int done;
    int nzero;
    float loss_sum;
};
__device__ Scratch g_s;                         // zeroed by ONE memset
__device__ unsigned g_pack[NROWS];              // (label<<18) | row

// -------- 1. histogram. 64 blocks (minimize contended global atomics) ----
__global__ void k_hist(const int* __restrict__ labels) {
    __shared__ int s_cnt[NCLUST];
    for (int i = threadIdx.x; i < NCLUST; i += blockDim.x) s_cnt[i] = 0;
    __syncthreads();
    const int4* l4 = (const int4*)labels;
    for (int r = blockIdx.x * blockDim.x + threadIdx.x; r < NROWS / 4;
         r += gridDim.x * blockDim.x) {
        int4 v = l4[r];
        atomicAdd(&s_cnt[v.x], 1);
        atomicAdd(&s_cnt[v.y], 1);
        atomicAdd(&s_cnt[v.z], 1);
        atomicAdd(&s_cnt[v.w], 1);
    }
    __syncthreads();
    for (int i = threadIdx.x; i < NCLUST; i += blockDim.x)
        if (s_cnt[i]) atomicAdd(&g_s.counts[i], s_cnt[i]);
}

// -------- 2. scatter (scan fused). 128 blocks x 256, 2048 rows/block ----
__global__ void __launch_bounds__(256) k_scatter(const int* __restrict__ labels) {
    __shared__ int s_hist[NCLUST];
    __shared__ int s_base[NCLUST];
    __shared__ int s_scan[256];
    const int t = threadIdx.x;

    int cv = (t < NCLUST) ? g_s.counts[t] : 0;
    s_scan[t] = cv;
    for (int i = t; i < NCLUST; i += 256) s_hist[i] = 0;
    if (blockIdx.x == 0 && t < NCLUST && cv == 0) atomicAdd(&g_s.nzero, 1);
    __syncthreads();
#pragma unroll
    for (int off = 1; off < 256; off <<= 1) {
        int add = (t >= off) ? s_scan[t - off] : 0;
        __syncthreads();
        s_scan[t] += add;
        __syncthreads();
    }

    const int r0 = blockIdx.x * 2048;
    int labs[8], rk[8];
#pragma unroll
    for (int u = 0; u < 8; u++) labs[u] = labels[r0 + u * 256 + t];
#pragma unroll
    for (int u = 0; u < 8; u++) rk[u] = atomicAdd(&s_hist[labs[u]], 1);
    __syncthreads();
    if (t < NCLUST) {
        int h = s_hist[t];
        if (h) s_base[t] = (s_scan[t] - cv) + atomicAdd(&g_s.cursor[t], h);
    }
    __syncthreads();
#pragma unroll
    for (int u = 0; u < 8; u++) {
        int c = labs[u];
        int p = s_base[c] + rk[u];
        g_pack[p] = ((unsigned)c << 18) | (unsigned)(r0 + u * 256 + t);
    }
}

// -------- 3. persistent segment sums (work-steal; no wave tail) --------
// 740 blocks pull 256-entry chunks: item in [0, 2*NCHUNK); y = item/NCHUNK.
__global__ void __launch_bounds__(256, 5) k_segsum(const float* __restrict__ xq,
                                                   const float* __restrict__ xk) {
    const int t = threadIdx.x;
    const int dq = (t & 63) * 4;      // dim-quad base
    const int sub = t >> 6;           // 0..3
    __shared__ int s_item;

    while (true) {
        if (t == 0) s_item = atomicAdd(&g_s.work, 1);
        __syncthreads();
        const int item = s_item;
        __syncthreads();
        if (item >= 2 * NCHUNK) break;

        const int y = (item >= NCHUNK);
        const int start = (y ? item - NCHUNK : item) * 256;
        const float* __restrict__ x = y ? xk : xq;
        float* sums = &g_s.sums[y][0];

        int cur = (int)(g_pack[start + sub] >> 18);
        float4 acc = make_float4(0.f, 0.f, 0.f, 0.f);

        for (int it = 0; it < 64; it += 8) {
            unsigned pk[8];
            float4 v[8];
#pragma unroll
            for (int u = 0; u < 8; u++)
                pk[u] = g_pack[start + sub + (it + u) * 4];
#pragma unroll
            for (int u = 0; u < 8; u++)
                v[u] = __ldcs((const float4*)&x[(size_t)(pk[u] & 0x3FFFFu) * DIM + dq]);
#pragma unroll
            for (int u = 0; u < 8; u++) {
                int lb = (int)(pk[u] >> 18);
                if (lb != cur) {
                    float* dst = &sums[cur * DIM + dq];
                    atomicAdd(dst + 0, acc.x);
                    atomicAdd(dst + 1, acc.y);
                    atomicAdd(dst + 2, acc.z);
                    atomicAdd(dst + 3, acc.w);
                    acc = make_float4(0.f, 0.f, 0.f, 0.f);
                    cur = lb;
                }
                acc.x += v[u].x;
                acc.y += v[u].y;
                acc.z += v[u].z;
                acc.w += v[u].w;
            }
        }
        float* dst = &sums[cur * DIM + dq];
        atomicAdd(dst + 0, acc.x);
        atomicAdd(dst + 1, acc.y);
        atomicAdd(dst + 2, acc.z);
        atomicAdd(dst + 3, acc.w);
    }
}

// -------- 4. loss on RAW sums, 1024 thr, two 3-j rounds + tail ----------
// dot(c_i,c_j) = dot(s_i,s_j)*inv_i*inv_j. 2 i-rows per block, grid 98.
// Epilogue: warps 0/1 each do one row's full logsumexp from smem.
__global__ void __launch_bounds__(1024) k_loss(float* out) {
    const int i0 = blockIdx.x * 2;
    const int i1 = i0 + 1;
    const int tid = threadIdx.x;
    const int lane = tid & 31, w = tid >> 5;
    __shared__ float s_q0[DIM], s_q1[DIM];
    __shared__ float s_row0[NCLUST], s_row1[NCLUST];
    __shared__ float s_n[NCLUST];
    __shared__ float s_dkraw[2], s_nk[2];

    const float* sq = &g_s.sums[0][0];
    const float* sk = &g_s.sums[1][0];

    if (tid < DIM) {
        s_q0[tid] = sq[i0 * DIM + tid];
        s_q1[tid] = sq[i1 * DIM + tid];
    }
    __syncthreads();

    const float4* q0v = (const float4*)s_q0;
    const float4* q1v = (const float4*)s_q1;
    const float4 a0 = q0v[lane], b0 = q0v[32 + lane];
    const float4 a1 = q1v[lane], b1 = q1v[32 + lane];

    // rounds r=0,1: j = w + (r*3+g)*32, g=0..2 (all < 192).
#pragma unroll
    for (int r = 0; r < 2; r++) {
        float4 va[3], vb[3];
        float p0[3], p1[3], nn[3];
#pragma unroll
        for (int g = 0; g < 3; g++) {
            const float4* vj = (const float4*)&sq[(w + (r * 3 + g) * 32) * DIM];
            va[g] = vj[lane];
            vb[g] = vj[32 + lane];
        }
#pragma unroll
        for (int g = 0; g < 3; g++) {
            p0[g] = va[g].x * a0.x + va[g].y * a0.y + va[g].z * a0.z + va[g].w * a0.w
                  + vb[g].x * b0.x + vb[g].y * b0.y + vb[g].z * b0.z + vb[g].w * b0.w;
            p1[g] = va[g].x * a1.x + va[g].y * a1.y + va[g].z * a1.z + va[g].w * a1.w
                  + vb[g].x * b1.x + vb[g].y * b1.y + vb[g].z * b1.z + vb[g].w * b1.w;
            nn[g] = va[g].x * va[g].x + va[g].y * va[g].y + va[g].z * va[g].z + va[g].w * va[g].w
                  + vb[g].x * vb[g].x + vb[g].y * vb[g].y + vb[g].z * vb[g].z + vb[g].w * vb[g].w;
        }
#pragma unroll
        for (int off = 16; off > 0; off >>= 1) {
#pragma unroll
            for (int g = 0; g < 3; g++) {
                p0[g] += __shfl_xor_sync(0xFFFFFFFFu, p0[g], off);
                p1[g] += __shfl_xor_sync(0xFFFFFFFFu, p1[g], off);
                nn[g] += __shfl_xor_sync(0xFFFFFFFFu, nn[g], off);
            }
        }
        if (lane == 0) {
#pragma unroll
            for (int g = 0; g < 3; g++) {
                int j = w + (r * 3 + g) * 32;
                s_row0[j] = p0[g];
                s_row1[j] = p1[g];
                s_n[j] = nn[g];
            }
        }
    }
    // tail: j = 192 + w for w < 4
    if (w < 4) {
        const int j = w + 192;
        const float4* vj = (const float4*)&sq[j * DIM];
        float4 va = vj[lane], vb = vj[32 + lane];
        float p0 = va.x * a0.x + va.y * a0.y + va.z * a0.z + va.w * a0.w
                 + vb.x * b0.x + vb.y * b0.y + vb.z * b0.z + vb.w * b0.w;
        float p1 = va.x * a1.x + va.y * a1.y + va.z * a1.z + va.w * a1.w
                 + vb.x * b1.x + vb.y * b1.y + vb.z * b1.z + vb.w * b1.w;
        float nn = va.x * va.x + va.y * va.y + va.z * va.z + va.w * va.w
                 + vb.x * vb.x + vb.y * vb.y + vb.z * vb.z + vb.w * vb.w;
#pragma unroll
        for (int off = 16; off > 0; off >>= 1) {
            p0 += __shfl_xor_sync(0xFFFFFFFFu, p0, off);
            p1 += __shfl_xor_sync(0xFFFFFFFFu, p1, off);
            nn += __shfl_xor_sync(0xFFFFFFFFu, nn, off);
        }
        if (lane == 0) { s_row0[j] = p0; s_row1[j] = p1; s_n[j] = nn; }
    }
    // k-diagonals (warps 4,5)
    if (w == 4 || w == 5) {
        const int sel = w - 4;
        const float4* vj = (const float4*)&sk[(sel ? i1 : i0) * DIM];
        float4 va = vj[lane], vb = vj[32 + lane];
        float4 ca = sel ? a1 : a0, cb = sel ? b1 : b0;
        float p = va.x * ca.x + va.y * ca.y + va.z * ca.z + va.w * ca.w
                + vb.x * cb.x + vb.y * cb.y + vb.z * cb.z + vb.w * cb.w;
        float nn = va.x * va.x + va.y * va.y + va.z * va.z + va.w * va.w
                 + vb.x * vb.x + vb.y * vb.y + vb.z * vb.z + vb.w * vb.w;
#pragma unroll
        for (int off = 16; off > 0; off >>= 1) {
            p += __shfl_xor_sync(0xFFFFFFFFu, p, off);
            nn += __shfl_xor_sync(0xFFFFFFFFu, nn, off);
        }
        if (lane == 0) { s_dkraw[sel] = p; s_nk[sel] = nn; }
    }
    __syncthreads();

    // scale + mask
    const float inv0 = 1.0f / fmaxf(sqrtf(s_n[i0]), EPSV);
    const float inv1 = 1.0f / fmaxf(sqrtf(s_n[i1]), EPSV);
    if (tid < NCLUST) {
        float invj = 1.0f / fmaxf(sqrtf(s_n[tid]), EPSV);
        float r0, r1;
        if (tid == i0)
            r0 = s_dkraw[0] * inv0 / fmaxf(sqrtf(s_nk[0]), EPSV) * TEMP_INV;
        else
            r0 = s_row0[tid] * inv0 * invj * TEMP_INV;
        if (tid == i1)
            r1 = s_dkraw[1] * inv1 / fmaxf(sqrtf(s_nk[1]), EPSV) * TEMP_INV;
        else
            r1 = s_row1[tid] * inv1 * invj * TEMP_INV;
        if (g_s.counts[tid] == 0) { r0 = -10.0f; r1 = -10.0f; }
        s_row0[tid] = r0;
        s_row1[tid] = r1;
    }
    __syncthreads();

    // epilogue: warp 0 -> row0, warp 1 -> row1; full 196-logsumexp per warp
    if (w < 2) {
        const float* rowp = w ? s_row1 : s_row0;
        float vals[7];
        float mx = -1e30f;
#pragma unroll
        for (int m = 0; m < 7; m++) {
            int j = lane + m * 32;
            vals[m] = (j < NCLUST) ? rowp[j] : -1e30f;
            mx = fmaxf(mx, vals[m]);
        }
#pragma unroll
        for (int off = 16; off > 0; off >>= 1)
            mx = fmaxf(mx, __shfl_xor_sync(0xFFFFFFFFu, mx, off));
        float es = 0.0f;
#pragma unroll
        for (int m = 0; m < 7; m++)
            es += __expf(vals[m] - mx);
#pragma unroll
        for (int off = 16; off > 0; off >>= 1)
            es += __shfl_xor_sync(0xFFFFFFFFu, es, off);
        if (lane == 0) {
            int i = w ? i1 : i0;
            if (g_s.counts[i] != 0) {
                float loss = -rowp[i] + mx + logf(es);
                atomicAdd(&g_s.loss_sum, loss);
            }
        }
    }
    __syncthreads();

    if (tid == 0) {
        __threadfence();
        int ticket = atomicAdd(&g_s.done, 1);
        if (ticket == NCLUST / 2 - 1) {
            float tot = atomicAdd(&g_s.loss_sum, 0.0f);
            out[0] = tot / ((float)NCLUST - (float)g_s.nzero);
        }
    }
}

extern "C" void kernel_launch(void* const* d_in, const int* in_sizes, int n_in,
                              void* d_out, int out_size) {
    const float* im_q = (const float*)d_in[0];
    const float* im_k = (const float*)d_in[1];
    const int* labels = (const int*)d_in[2];
    float* out = (float*)d_out;

    void* p_s = 0;
    cudaGetSymbolAddress(&p_s, g_s);
    cudaMemsetAsync(p_s, 0, sizeof(Scratch));

    k_hist<<<64, 256>>>(labels);
    k_scatter<<<128, 256>>>(labels);
    k_segsum<<<740, 256>>>(im_q, im_k);
    k_loss<<<NCLUST / 2, 1024>>>(out);
}

// round 15
// speedup vs baseline: 1.1289x; 1.0641x over previous
#include <cuda_runtime.h>
#include <math.h>

#define NCLUST 196
#define DIM 256
#define NROWS 262144
#define REGION 1536            // slots per cluster (6 chunks of 256)
#define RCHUNK 6
#define NCHUNKP (NCLUST * RCHUNK)     // 1176 chunks per matrix
#define NPACK (NCLUST * REGION)       // 301056
#define TEMP_INV 2.0f          // 1/TEMPERATURE
#define EPSV 1e-12f

// -------- scratch (device globals; no allocation allowed) --------
struct Scratch {
    float sums[2][NCLUST * DIM];   // [q,k] raw segment sums
    unsigned pack[NPACK];          // row+1 per slot; 0 = invalid (memset)
    int cursor[NCLUST];            // fill level per cluster == counts
    int work;                      // segsum work-steal counter
    int done;
    int nzero;
    float loss_sum;
};
__device__ Scratch g_s;                         // zeroed by ONE memset

// -------- 1. scatter into padded per-cluster regions. 128 x 256 --------
__global__ void __launch_bounds__(256) k_scatter(const int* __restrict__ labels) {
    __shared__ int s_hist[NCLUST];
    __shared__ int s_base[NCLUST];
    const int t = threadIdx.x;
    for (int i = t; i < NCLUST; i += 256) s_hist[i] = 0;
    __syncthreads();

    const int r0 = blockIdx.x * 2048;
    int labs[8], rk[8];
#pragma unroll
    for (int u = 0; u < 8; u++) labs[u] = labels[r0 + u * 256 + t];
#pragma unroll
    for (int u = 0; u < 8; u++) rk[u] = atomicAdd(&s_hist[labs[u]], 1);
    __syncthreads();
    if (t < NCLUST) {
        int h = s_hist[t];
        if (h) s_base[t] = t * REGION + atomicAdd(&g_s.cursor[t], h);
    }
    __syncthreads();
#pragma unroll
    for (int u = 0; u < 8; u++)
        g_s.pack[s_base[labs[u]] + rk[u]] = (unsigned)(r0 + u * 256 + t + 1);
}

// -------- 2. persistent segment sums (work-steal, label-free) ----------
// item in [0, 2*NCHUNKP): y = item/NCHUNKP, chunk ci = item%NCHUNKP,
// cluster = ci/6. Chunk = 256 slots of ONE cluster; predicated gather.
__global__ void __launch_bounds__(256, 5) k_segsum(const float* __restrict__ xq,
                                                   const float* __restrict__ xk) {
    const int t = threadIdx.x;
    const int dq = (t & 63) * 4;      // dim-quad base
    const int sub = t >> 6;           // 0..3
    __shared__ int s_item;

    while (true) {
        if (t == 0) s_item = atomicAdd(&g_s.work, 1);
        __syncthreads();
        const int item = s_item;
        __syncthreads();
        if (item >= 2 * NCHUNKP) break;

        const int y = (item >= NCHUNKP);
        const int ci = y ? item - NCHUNKP : item;
        const int clu = ci / RCHUNK;
        const int start = ci * 256;
        const float* __restrict__ x = y ? xk : xq;

        if (g_s.pack[start] == 0) continue;   // fully-empty chunk (uniform)

        float4 acc = make_float4(0.f, 0.f, 0.f, 0.f);
        for (int it = 0; it < 64; it += 8) {
            unsigned pk[8];
            float4 v[8];
#pragma unroll
            for (int u = 0; u < 8; u++)
                pk[u] = g_s.pack[start + sub + (it + u) * 4];
#pragma unroll
            for (int u = 0; u < 8; u++) {
                if (pk[u])
                    v[u] = __ldcs((const float4*)&x[(size_t)(pk[u] - 1) * DIM + dq]);
                else
                    v[u] = make_float4(0.f, 0.f, 0.f, 0.f);
            }
#pragma unroll
            for (int u = 0; u < 8; u++) {
                acc.x += v[u].x;
                acc.y += v[u].y;
                acc.z += v[u].z;
                acc.w += v[u].w;
            }
        }
        float* dst = &g_s.sums[y][clu * DIM + dq];
        asm volatile("red.global.add.v4.f32 [%0], {%1,%2,%3,%4};"
                     :: "l"(dst), "f"(acc.x), "f"(acc.y),
                        "f"(acc.z), "f"(acc.w) : "memory");
    }
}

// -------- 3. loss on RAW sums, 1024 thr, two 3-j rounds + tail ----------
// dot(c_i,c_j) = dot(s_i,s_j)*inv_i*inv_j. 2 i-rows per block, grid 98.
// Epilogue: warps 0/1 each do one row's full logsumexp from smem.
__global__ void __launch_bounds__(1024) k_loss(float* out) {
    const int i0 = blockIdx.x * 2;
    const int i1 = i0 + 1;
    const int tid = threadIdx.x;
    const int lane = tid & 31, w = tid >> 5;
    __shared__ float s_q0[DIM], s_q1[DIM];
    __shared__ float s_row0[NCLUST], s_row1[NCLUST];
    __shared__ float s_n[NCLUST];
    __shared__ float s_dkraw[2], s_nk[2];

    const float* sq = &g_s.sums[0][0];
    const float* sk = &g_s.sums[1][0];

    // block 0 computes n_zero (cursor holds final counts)
    if (blockIdx.x == 0 && tid < NCLUST && g_s.cursor[tid] == 0)
        atomicAdd(&g_s.nzero, 1);

    if (tid < DIM) {
        s_q0[tid] = sq[i0 * DIM + tid];
        s_q1[tid] = sq[i1 * DIM + tid];
    }
    __syncthreads();

    const float4* q0v = (const float4*)s_q0;
    const float4* q1v = (const float4*)s_q1;
    const float4 a0 = q0v[lane], b0 = q0v[32 + lane];
    const float4 a1 = q1v[lane], b1 = q1v[32 + lane];

    // rounds r=0,1: j = w + (r*3+g)*32, g=0..2 (all < 192).
#pragma unroll
    for (int r = 0; r < 2; r++) {
        float4 va[3], vb[3];
        float p0[3], p1[3], nn[3];
#pragma unroll
        for (int g = 0; g < 3; g++) {
            const float4* vj = (const float4*)&sq[(w + (r * 3 + g) * 32) * DIM];
            va[g] = vj[lane];
            vb[g] = vj[32 + lane];
        }
#pragma unroll
        for (int g = 0; g < 3; g++) {
            p0[g] = va[g].x * a0.x + va[g].y * a0.y + va[g].z * a0.z + va[g].w * a0.w
                  + vb[g].x * b0.x + vb[g].y * b0.y + vb[g].z * b0.z + vb[g].w * b0.w;
            p1[g] = va[g].x * a1.x + va[g].y * a1.y + va[g].z * a1.z + va[g].w * a1.w
                  + vb[g].x * b1.x + vb[g].y * b1.y + vb[g].z * b1.z + vb[g].w * b1.w;
            nn[g] = va[g].x * va[g].x + va[g].y * va[g].y + va[g].z * va[g].z + va[g].w * va[g].w
                  + vb[g].x * vb[g].x + vb[g].y * vb[g].y + vb[g].z * vb[g].z + vb[g].w * vb[g].w;
        }
#pragma unroll
        for (int off = 16; off > 0; off >>= 1) {
#pragma unroll
            for (int g = 0; g < 3; g++) {
                p0[g] += __shfl_xor_sync(0xFFFFFFFFu, p0[g], off);
                p1[g] += __shfl_xor_sync(0xFFFFFFFFu, p1[g], off);
                nn[g] += __shfl_xor_sync(0xFFFFFFFFu, nn[g], off);
            }
        }
        if (lane == 0) {
#pragma unroll
            for (int g = 0; g < 3; g++) {
                int j = w + (r * 3 + g) * 32;
                s_row0[j] = p0[g];
                s_row1[j] = p1[g];
                s_n[j] = nn[g];
            }
        }
    }
    // tail: j = 192 + w for w < 4
    if (w < 4) {
        const int j = w + 192;
        const float4* vj = (const float4*)&sq[j * DIM];
        float4 va = vj[lane], vb = vj[32 + lane];
        float p0 = va.x * a0.x + va.y * a0.y + va.z * a0.z + va.w * a0.w
                 + vb.x * b0.x + vb.y * b0.y + vb.z * b0.z + vb.w * b0.w;
        float p1 = va.x * a1.x + va.y * a1.y + va.z * a1.z + va.w * a1.w
                 + vb.x * b1.x + vb.y * b1.y + vb.z * b1.z + vb.w * b1.w;
        float nn = va.x * va.x + va.y * va.y + va.z * va.z + va.w * va.w
                 + vb.x * vb.x + vb.y * vb.y + vb.z * vb.z + vb.w * vb.w;
#pragma unroll
        for (int off = 16; off > 0; off >>= 1) {
            p0 += __shfl_xor_sync(0xFFFFFFFFu, p0, off);
            p1 += __shfl_xor_sync(0xFFFFFFFFu, p1, off);
            nn += __shfl_xor_sync(0xFFFFFFFFu, nn, off);
        }
        if (lane == 0) { s_row0[j] = p0; s_row1[j] = p1; s_n[j] = nn; }
    }
    // k-diagonals (warps 4,5)
    if (w == 4 || w == 5) {
        const int sel = w - 4;
        const float4* vj = (const float4*)&sk[(sel ? i1 : i0) * DIM];
        float4 va = vj[lane], vb = vj[32 + lane];
        float4 ca = sel ? a1 : a0, cb = sel ? b1 : b0;
        float p = va.x * ca.x + va.y * ca.y + va.z * ca.z + va.w * ca.w
                + vb.x * cb.x + vb.y * cb.y + vb.z * cb.z + vb.w * cb.w;
        float nn = va.x * va.x + va.y * va.y + va.z * va.z + va.w * va.w
                 + vb.x * vb.x + vb.y * vb.y + vb.z * vb.z + vb.w * vb.w;
#pragma unroll
        for (int off = 16; off > 0; off >>= 1) {
            p += __shfl_xor_sync(0xFFFFFFFFu, p, off);
            nn += __shfl_xor_sync(0xFFFFFFFFu, nn, off);
        }
        if (lane == 0) { s_dkraw[sel] = p; s_nk[sel] = nn; }
    }
    __syncthreads();

    // scale + mask
    const float inv0 = 1.0f / fmaxf(sqrtf(s_n[i0]), EPSV);
    const float inv1 = 1.0f / fmaxf(sqrtf(s_n[i1]), EPSV);
    if (tid < NCLUST) {
        float invj = 1.0f / fmaxf(sqrtf(s_n[tid]), EPSV);
        float r0, r1;
        if (tid == i0)
            r0 = s_dkraw[0] * inv0 / fmaxf(sqrtf(s_nk[0]), EPSV) * TEMP_INV;
        else
            r0 = s_row0[tid] * inv0 * invj * TEMP_INV;
        if (tid == i1)
            r1 = s_dkraw[1] * inv1 / fmaxf(sqrtf(s_nk[1]), EPSV) * TEMP_INV;
        else
            r1 = s_row1[tid] * inv1 * invj * TEMP_INV;
        if (g_s.cursor[tid] == 0) { r0 = -10.0f; r1 = -10.0f; }
        s_row0[tid] = r0;
        s_row1[tid] = r1;
    }
    __syncthreads();

    // epilogue: warp 0 -> row0, warp 1 -> row1; full 196-logsumexp per warp
    if (w < 2) {
        const float* rowp = w ? s_row1 : s_row0;
        float vals[7];
        float mx = -1e30f;
#pragma unroll
        for (int m = 0; m < 7; m++) {
            int j = lane + m * 32;
            vals[m] = (j < NCLUST) ? rowp[j] : -1e30f;
            mx = fmaxf(mx, vals[m]);
        }
#pragma unroll
        for (int off = 16; off > 0; off >>= 1)
            mx = fmaxf(mx, __shfl_xor_sync(0xFFFFFFFFu, mx, off));
        float es = 0.0f;
#pragma unroll
        for (int m = 0; m < 7; m++)
            es += __expf(vals[m] - mx);
#pragma unroll
        for (int off = 16; off > 0; off >>= 1)
            es += __shfl_xor_sync(0xFFFFFFFFu, es, off);
        if (lane == 0) {
            int i = w ? i1 : i0;
            if (g_s.cursor[i] != 0) {
                float loss = -rowp[i] + mx + logf(es);
                atomicAdd(&g_s.loss_sum, loss);
            }
        }
    }
    __syncthreads();

    if (tid == 0) {
        __threadfence();
        int ticket = atomicAdd(&g_s.done, 1);
        if (ticket == NCLUST / 2 - 1) {
            float tot = atomicAdd(&g_s.loss_sum, 0.0f);
            out[0] = tot / ((float)NCLUST - (float)g_s.nzero);
        }
    }
}

extern "C" void kernel_launch(void* const* d_in, const int* in_sizes, int n_in,
                              void* d_out, int out_size) {
    const float* im_q = (const float*)d_in[0];
    const float* im_k = (const float*)d_in[1];
    const int* labels = (const int*)d_in[2];
    float* out = (float*)d_out;

    void* p_s = 0;
    cudaGetSymbolAddress(&p_s, g_s);
    cudaMemsetAsync(p_s, 0, sizeof(Scratch));

    k_scatter<<<128, 256>>>(labels);
    k_segsum<<<740, 256>>>(im_q, im_k);
    k_loss<<<NCLUST / 2, 1024>>>(out);
}

// round 16
// speedup vs baseline: 1.1354x; 1.0058x over previous
#include <cuda_runtime.h>
#include <math.h>

#define NCLUST 196
#define DIM 256
#define NROWS 262144
#define REGION 1536            // slots per cluster (6 chunks of 256)
#define RCHUNK 6
#define NCHUNKP (NCLUST * RCHUNK)     // 1176 chunks per matrix
#define NPACK (NCLUST * REGION)       // 301056
#define TEMP_INV 2.0f          // 1/TEMPERATURE
#define EPSV 1e-12f

// -------- scratch (device globals; no allocation allowed) --------
struct Scratch {
    float sums[2][NCLUST * DIM];   // [q,k] raw segment sums
    unsigned pack[NPACK];          // row+1 per slot; 0 = invalid (memset)
    int cursor[NCLUST];            // fill level per cluster == counts
    int work;                      // segsum work-steal counter
    int done;
    int nzero;
    float loss_sum;
};
__device__ Scratch g_s;                         // zeroed by ONE memset

// -------- 1. scatter into padded per-cluster regions. 128 x 512 --------
// 4 rows/thread: shorter smem-atomic dependency chain, 16 warps/SM.
__global__ void __launch_bounds__(512) k_scatter(const int* __restrict__ labels) {
    __shared__ int s_hist[NCLUST];
    __shared__ int s_base[NCLUST];
    const int t = threadIdx.x;
    for (int i = t; i < NCLUST; i += 512) s_hist[i] = 0;
    __syncthreads();

    const int r0 = blockIdx.x * 2048;
    int labs[4], rk[4];
#pragma unroll
    for (int u = 0; u < 4; u++) labs[u] = labels[r0 + u * 512 + t];
#pragma unroll
    for (int u = 0; u < 4; u++) rk[u] = atomicAdd(&s_hist[labs[u]], 1);
    __syncthreads();
    if (t < NCLUST) {
        int h = s_hist[t];
        if (h) s_base[t] = t * REGION + atomicAdd(&g_s.cursor[t], h);
    }
    __syncthreads();
#pragma unroll
    for (int u = 0; u < 4; u++)
        g_s.pack[s_base[labs[u]] + rk[u]] = (unsigned)(r0 + u * 512 + t + 1);
}

// -------- 2. persistent segment sums (work-steal, label-free) ----------
// item in [0, 2*NCHUNKP): y = item/NCHUNKP, chunk ci = item%NCHUNKP,
// cluster = ci/6. Chunk = 256 slots of ONE cluster; predicated gather.
__global__ void __launch_bounds__(256, 5) k_segsum(const float* __restrict__ xq,
                                                   const float* __restrict__ xk) {
    const int t = threadIdx.x;
    const int dq = (t & 63) * 4;      // dim-quad base
    const int sub = t >> 6;           // 0..3
    __shared__ int s_item;

    while (true) {
        if (t == 0) s_item = atomicAdd(&g_s.work, 1);
        __syncthreads();
        const int item = s_item;
        __syncthreads();
        if (item >= 2 * NCHUNKP) break;

        const int y = (item >= NCHUNKP);
        const int ci = y ? item - NCHUNKP : item;
        const int clu = ci / RCHUNK;
        const int start = ci * 256;
        const float* __restrict__ x = y ? xk : xq;

        if (g_s.pack[start] == 0) continue;   // fully-empty chunk (uniform)

        float4 acc = make_float4(0.f, 0.f, 0.f, 0.f);
        for (int it = 0; it < 64; it += 8) {
            unsigned pk[8];
            float4 v[8];
#pragma unroll
            for (int u = 0; u < 8; u++)
                pk[u] = g_s.pack[start + sub + (it + u) * 4];
#pragma unroll
            for (int u = 0; u < 8; u++) {
                if (pk[u])
                    v[u] = __ldcs((const float4*)&x[(size_t)(pk[u] - 1) * DIM + dq]);
                else
                    v[u] = make_float4(0.f, 0.f, 0.f, 0.f);
            }
#pragma unroll
            for (int u = 0; u < 8; u++) {
                acc.x += v[u].x;
                acc.y += v[u].y;
                acc.z += v[u].z;
                acc.w += v[u].w;
            }
        }
        float* dst = &g_s.sums[y][clu * DIM + dq];
        asm volatile("red.global.add.v4.f32 [%0], {%1,%2,%3,%4};"
                     :: "l"(dst), "f"(acc.x), "f"(acc.y),
                        "f"(acc.z), "f"(acc.w) : "memory");
    }
}

// -------- 3. loss on RAW sums, 1024 thr, two 3-j rounds + tail ----------
// dot(c_i,c_j) = dot(s_i,s_j)*inv_i*inv_j. 2 i-rows per block, grid 98.
// Epilogue: warps 0/1 each do one row's full logsumexp from smem.
__global__ void __launch_bounds__(1024) k_loss(float* out) {
    const int i0 = blockIdx.x * 2;
    const int i1 = i0 + 1;
    const int tid = threadIdx.x;
    const int lane = tid & 31, w = tid >> 5;
    __shared__ float s_q0[DIM], s_q1[DIM];
    __shared__ float s_row0[NCLUST], s_row1[NCLUST];
    __shared__ float s_n[NCLUST];
    __shared__ float s_dkraw[2], s_nk[2];

    const float* sq = &g_s.sums[0][0];
    const float* sk = &g_s.sums[1][0];

    // block 0 computes n_zero (cursor holds final counts)
    if (blockIdx.x == 0 && tid < NCLUST && g_s.cursor[tid] == 0)
        atomicAdd(&g_s.nzero, 1);

    if (tid < DIM) {
        s_q0[tid] = sq[i0 * DIM + tid];
        s_q1[tid] = sq[i1 * DIM + tid];
    }
    __syncthreads();

    const float4* q0v = (const float4*)s_q0;
    const float4* q1v = (const float4*)s_q1;
    const float4 a0 = q0v[lane], b0 = q0v[32 + lane];
    const float4 a1 = q1v[lane], b1 = q1v[32 + lane];

    // rounds r=0,1: j = w + (r*3+g)*32, g=0..2 (all < 192).
#pragma unroll
    for (int r = 0; r < 2; r++) {
        float4 va[3], vb[3];
        float p0[3], p1[3], nn[3];
#pragma unroll
        for (int g = 0; g < 3; g++) {
            const float4* vj = (const float4*)&sq[(w + (r * 3 + g) * 32) * DIM];
            va[g] = vj[lane];
            vb[g] = vj[32 + lane];
        }
#pragma unroll
        for (int g = 0; g < 3; g++) {
            p0[g] = va[g].x * a0.x + va[g].y * a0.y + va[g].z * a0.z + va[g].w * a0.w
                  + vb[g].x * b0.x + vb[g].y * b0.y + vb[g].z * b0.z + vb[g].w * b0.w;
            p1[g] = va[g].x * a1.x + va[g].y * a1.y + va[g].z * a1.z + va[g].w * a1.w
                  + vb[g].x * b1.x + vb[g].y * b1.y + vb[g].z * b1.z + vb[g].w * b1.w;
            nn[g] = va[g].x * va[g].x + va[g].y * va[g].y + va[g].z * va[g].z + va[g].w * va[g].w
                  + vb[g].x * vb[g].x + vb[g].y * vb[g].y + vb[g].z * vb[g].z + vb[g].w * vb[g].w;
        }
#pragma unroll
        for (int off = 16; off > 0; off >>= 1) {
#pragma unroll
            for (int g = 0; g < 3; g++) {
                p0[g] += __shfl_xor_sync(0xFFFFFFFFu, p0[g], off);
                p1[g] += __shfl_xor_sync(0xFFFFFFFFu, p1[g], off);
                nn[g] += __shfl_xor_sync(0xFFFFFFFFu, nn[g], off);
            }
        }
        if (lane == 0) {
#pragma unroll
            for (int g = 0; g < 3; g++) {
                int j = w + (r * 3 + g) * 32;
                s_row0[j] = p0[g];
                s_row1[j] = p1[g];
                s_n[j] = nn[g];
            }
        }
    }
    // tail: j = 192 + w for w < 4
    if (w < 4) {
        const int j = w + 192;
        const float4* vj = (const float4*)&sq[j * DIM];
        float4 va = vj[lane], vb = vj[32 + lane];
        float p0 = va.x * a0.x + va.y * a0.y + va.z * a0.z + va.w * a0.w
                 + vb.x * b0.x + vb.y * b0.y + vb.z * b0.z + vb.w * b0.w;
        float p1 = va.x * a1.x + va.y * a1.y + va.z * a1.z + va.w * a1.w
                 + vb.x * b1.x + vb.y * b1.y + vb.z * b1.z + vb.w * b1.w;
        float nn = va.x * va.x + va.y * va.y + va.z * va.z + va.w * va.w
                 + vb.x * vb.x + vb.y * vb.y + vb.z * vb.z + vb.w * vb.w;
#pragma unroll
        for (int off = 16; off > 0; off >>= 1) {
            p0 += __shfl_xor_sync(0xFFFFFFFFu, p0, off);
            p1 += __shfl_xor_sync(0xFFFFFFFFu, p1, off);
            nn += __shfl_xor_sync(0xFFFFFFFFu, nn, off);
        }
        if (lane == 0) { s_row0[j] = p0; s_row1[j] = p1; s_n[j] = nn; }
    }
    // k-diagonals (warps 4,5)
    if (w == 4 || w == 5) {
        const int sel = w - 4;
        const float4* vj = (const float4*)&sk[(sel ? i1 : i0) * DIM];
        float4 va = vj[lane], vb = vj[32 + lane];
        float4 ca = sel ? a1 : a0, cb = sel ? b1 : b0;
        float p = va.x * ca.x + va.y * ca.y + va.z * ca.z + va.w * ca.w
                + vb.x * cb.x + vb.y * cb.y + vb.z * cb.z + vb.w * cb.w;
        float nn = va.x * va.x + va.y * va.y + va.z * va.z + va.w * va.w
                 + vb.x * vb.x + vb.y * vb.y + vb.z * vb.z + vb.w * vb.w;
#pragma unroll
        for (int off = 16; off > 0; off >>= 1) {
            p += __shfl_xor_sync(0xFFFFFFFFu, p, off);
            nn += __shfl_xor_sync(0xFFFFFFFFu, nn, off);
        }
        if (lane == 0) { s_dkraw[sel] = p; s_nk[sel] = nn; }
    }
    __syncthreads();

    // scale + mask
    const float inv0 = 1.0f / fmaxf(sqrtf(s_n[i0]), EPSV);
    const float inv1 = 1.0f / fmaxf(sqrtf(s_n[i1]), EPSV);
    if (tid < NCLUST) {
        float invj = 1.0f / fmaxf(sqrtf(s_n[tid]), EPSV);
        float r0, r1;
        if (tid == i0)
            r0 = s_dkraw[0] * inv0 / fmaxf(sqrtf(s_nk[0]), EPSV) * TEMP_INV;
        else
            r0 = s_row0[tid] * inv0 * invj * TEMP_INV;
        if (tid == i1)
            r1 = s_dkraw[1] * inv1 / fmaxf(sqrtf(s_nk[1]), EPSV) * TEMP_INV;
        else
            r1 = s_row1[tid] * inv1 * invj * TEMP_INV;
        if (g_s.cursor[tid] == 0) { r0 = -10.0f; r1 = -10.0f; }
        s_row0[tid] = r0;
        s_row1[tid] = r1;
    }
    __syncthreads();

    // epilogue: warp 0 -> row0, warp 1 -> row1; full 196-logsumexp per warp
    if (w < 2) {
        const float* rowp = w ? s_row1 : s_row0;
        float vals[7];
        float mx = -1e30f;
#pragma unroll
        for (int m = 0; m < 7; m++) {
            int j = lane + m * 32;
            vals[m] = (j < NCLUST) ? rowp[j] : -1e30f;
            mx = fmaxf(mx, vals[m]);
        }
#pragma unroll
        for (int off = 16; off > 0; off >>= 1)
            mx = fmaxf(mx, __shfl_xor_sync(0xFFFFFFFFu, mx, off));
        float es = 0.0f;
#pragma unroll
        for (int m = 0; m < 7; m++)
            es += __expf(vals[m] - mx);
#pragma unroll
        for (int off = 16; off > 0; off >>= 1)
            es += __shfl_xor_sync(0xFFFFFFFFu, es, off);
        if (lane == 0) {
            int i = w ? i1 : i0;
            if (g_s.cursor[i] != 0) {
                float loss = -rowp[i] + mx + logf(es);
                atomicAdd(&g_s.loss_sum, loss);
            }
        }
    }
    __syncthreads();

    if (tid == 0) {
        __threadfence();
        int ticket = atomicAdd(&g_s.done, 1);
        if (ticket == NCLUST / 2 - 1) {
            float tot = atomicAdd(&g_s.loss_sum, 0.0f);
            out[0] = tot / ((float)NCLUST - (float)g_s.nzero);
        }
    }
}

extern "C" void kernel_launch(void* const* d_in, const int* in_sizes, int n_in,
                              void* d_out, int out_size) {
    const float* im_q = (const float*)d_in[0];
    const float* im_k = (const float*)d_in[1];
    const int* labels = (const int*)d_in[2];
    float* out = (float*)d_out;

    void* p_s = 0;
    cudaGetSymbolAddress(&p_s, g_s);
    cudaMemsetAsync(p_s, 0, sizeof(Scratch));

    k_scatter<<<128, 512>>>(labels);
    k_segsum<<<740, 256>>>(im_q, im_k);
    k_loss<<<NCLUST / 2, 1024>>>(out);
}